// round 15
// baseline (speedup 1.0000x reference)
#include <cuda_runtime.h>
#include <cstdint>
#include <cstddef>

#define DEV __device__ __forceinline__
#define NB   8
#define HW   225
#define NC   192
#define NT   113
#define NTOK (NB*HW*HW)
#define FT   16

__device__ float g_h[NB*HW*HW*NC];
__device__ float g_w[NB*HW*HW*NC];
__device__ float g_xsum[NB*NC];
__device__ float g_hwsum[NB*NC];
__device__ float g_a[3*NB*NC];

typedef unsigned long long u64;

DEV u64 pack2(float a, float b){
    u64 r; asm("mov.b64 %0, {%1, %2};" : "=l"(r)
               : "r"(__float_as_uint(a)), "r"(__float_as_uint(b))); return r;
}
DEV u64 dup2(float a){
    u64 r; asm("mov.b64 %0, {%1, %1};" : "=l"(r) : "r"(__float_as_uint(a))); return r;
}
DEV float2 unpk(u64 v){
    unsigned lo, hi; asm("mov.b64 {%0, %1}, %2;" : "=r"(lo), "=r"(hi) : "l"(v));
    return make_float2(__uint_as_float(lo), __uint_as_float(hi));
}
DEV void fma2(u64 &d, u64 a, u64 b){
    asm("fma.rn.f32x2 %0, %1, %2, %0;" : "+l"(d) : "l"(a), "l"(b));
}

// ---- cp.async helpers ----
DEV void cpa16(void* sdst, const void* gsrc){
    unsigned a = (unsigned)__cvta_generic_to_shared(sdst);
    asm volatile("cp.async.cg.shared.global [%0], [%1], 16;" :: "r"(a), "l"(gsrc));
}
DEV void cpa_commit(){ asm volatile("cp.async.commit_group;"); }
template<int N> DEV void cpa_wait(){ asm volatile("cp.async.wait_group %0;" :: "n"(N)); }

__global__ void zero_kernel(){
    int i = blockIdx.x*blockDim.x + threadIdx.x;
    if (i < NB*NC){ g_xsum[i] = 0.f; g_hwsum[i] = 0.f; }
}

__global__ void xsum_kernel(const float* __restrict__ x){
    int i = blockIdx.x, b = blockIdx.y, ch = threadIdx.x;
    const float* p = x + ((size_t)((b*HW + i)*HW))*NC + ch;
    float s = 0.f;
    for (int w = 0; w < HW; w++) s += p[(size_t)w*NC];
    atomicAdd(&g_xsum[b*NC + ch], s);
}

// Cooperative branch kernel, 3 blocks/SM (<=84 regs). 8 warps/block, each
// warp = 8 tokens of tile j. Single 36.8 KB weight buffer staged via
// cp.async. GEMM2 runs as two 4-token register passes to cap accumulators.
template<int AXIS>
__global__ void __launch_bounds__(256, 3)
branch_kernel(const float* __restrict__ x,  const float* __restrict__ w1,
              const float* __restrict__ gln, const float* __restrict__ bln,
              const float* __restrict__ w2,  const float* __restrict__ b2)
{
    extern __shared__ __align__(16) float smem[];
    float* ws = smem;                                      // 9216 floats
    float* xw = smem + 9216 + (threadIdx.x >> 5) * 1152;   // per-warp 96*12

    const int tid  = threadIdx.x;
    const int lane = tid & 31;
    const int b = blockIdx.z, j = blockIdx.y;
    const int p0 = blockIdx.x*64 + (tid >> 5)*8;
    float* obuf = (AXIS == 0) ? g_h : g_w;
    const int srcA = (j + HW - 2) % HW;
    const int srcB = (j + NT - 2) % HW;

    // ================= GEMM1: 384 -> 96, 4 chunks of 96 k =================
    u64 acc1[4][3];
    #pragma unroll
    for (int u = 0; u < 4; u++){ acc1[u][0]=0; acc1[u][1]=0; acc1[u][2]=0; }

    for (int kc = 0; kc < 4; kc++){
        __syncthreads();   // previous ws consumers done
        {   // stage w1 rows [kc*96, +96) -> ws (contiguous)
            const float4* src = (const float4*)(w1 + kc*9216) + tid;
            float4* dst = (float4*)ws + tid;
            #pragma unroll
            for (int i = 0; i < 9; i++) cpa16(dst + 256*i, src + 256*i);
            cpa_commit();
        }
        {   // stage x chunk kc into xw (per-warp), overlaps cp.async
            const int src = (kc < 2) ? srcA : srcB;
            const int choff = (kc & 1) * 96;
            #pragma unroll
            for (int t = 0; t < 8; t++){
                int pos = p0 + t; if (pos > HW-1) pos = HW-1;
                unsigned base;
                if (AXIS == 0) base = (unsigned)((b*HW + src)*HW + pos)*NC + choff;
                else           base = (unsigned)((b*HW + pos)*HW + src)*NC + choff;
                #pragma unroll
                for (int i = 0; i < 3; i++){
                    int cl = lane + 32*i;
                    xw[cl*12 + t] = x[base + cl];
                }
            }
        }
        cpa_wait<0>();
        __syncthreads();

        #pragma unroll 4
        for (int kk = 0; kk < 96; kk++){
            const float* wr = ws + kk*96;
            u64 wd0 = dup2(wr[lane]);
            u64 wd1 = dup2(wr[lane+32]);
            u64 wd2 = dup2(wr[lane+64]);
            const ulonglong2* xp = (const ulonglong2*)(xw + kk*12);
            ulonglong2 xa = xp[0], xb = xp[1];
            fma2(acc1[0][0], xa.x, wd0); fma2(acc1[0][1], xa.x, wd1); fma2(acc1[0][2], xa.x, wd2);
            fma2(acc1[1][0], xa.y, wd0); fma2(acc1[1][1], xa.y, wd1); fma2(acc1[1][2], xa.y, wd2);
            fma2(acc1[2][0], xb.x, wd0); fma2(acc1[2][1], xb.x, wd1); fma2(acc1[2][2], xb.x, wd2);
            fma2(acc1[3][0], xb.y, wd0); fma2(acc1[3][1], xb.y, wd1); fma2(acc1[3][2], xb.y, wd2);
        }
    }

    // ---- LayerNorm(96) + relu -> hs (overlays xw, dead after GEMM1) ----
    __syncwarp();
    {
        float gv0 = gln[lane], gv1 = gln[lane+32], gv2 = gln[lane+64];
        float bv0 = bln[lane], bv1 = bln[lane+32], bv2 = bln[lane+64];
        u64* hp = (u64*)xw;
        #pragma unroll
        for (int u = 0; u < 4; u++){
            float2 v0 = unpk(acc1[u][0]), v1 = unpk(acc1[u][1]), v2 = unpk(acc1[u][2]);
            float sx = v0.x+v1.x+v2.x, sy = v0.y+v1.y+v2.y;
            float qx = v0.x*v0.x+v1.x*v1.x+v2.x*v2.x;
            float qy = v0.y*v0.y+v1.y*v1.y+v2.y*v2.y;
            #pragma unroll
            for (int o = 16; o > 0; o >>= 1){
                sx += __shfl_xor_sync(0xffffffffu, sx, o);
                sy += __shfl_xor_sync(0xffffffffu, sy, o);
                qx += __shfl_xor_sync(0xffffffffu, qx, o);
                qy += __shfl_xor_sync(0xffffffffu, qy, o);
            }
            const float inv = 1.0f/96.0f;
            float mx = sx*inv, my = sy*inv;
            float rx = rsqrtf(fmaxf(qx*inv - mx*mx, 0.f) + 1e-6f);
            float ry = rsqrtf(fmaxf(qy*inv - my*my, 0.f) + 1e-6f);
            float hx, hy;
            hx = fmaxf((v0.x-mx)*rx*gv0+bv0, 0.f); hy = fmaxf((v0.y-my)*ry*gv0+bv0, 0.f);
            hp[lane*6 + u] = pack2(hx, hy);
            hx = fmaxf((v1.x-mx)*rx*gv1+bv1, 0.f); hy = fmaxf((v1.y-my)*ry*gv1+bv1, 0.f);
            hp[(lane+32)*6 + u] = pack2(hx, hy);
            hx = fmaxf((v2.x-mx)*rx*gv2+bv2, 0.f); hy = fmaxf((v2.y-my)*ry*gv2+bv2, 0.f);
            hp[(lane+64)*6 + u] = pack2(hx, hy);
        }
    }
    __syncwarp();

    // ====== GEMM2: 96 -> 384, 2 output halves x 2 token-passes of 4 ====
    for (int half = 0; half < 2; half++){
        for (int tp = 0; tp < 2; tp++){
            u64 acc2[4][3];
            #pragma unroll
            for (int t = 0; t < 4; t++){ acc2[t][0]=0; acc2[t][1]=0; acc2[t][2]=0; }

            for (int kc2 = 0; kc2 < 2; kc2++){
                __syncthreads();
                {   // stage w2 rows [kc2*48,+48) x cols [half*192,+192)
                    #pragma unroll
                    for (int ii = 0; ii < 9; ii++){
                        int i = tid + 256*ii;
                        int r = i/48, c4 = i%48;
                        cpa16((float4*)ws + i,
                              (const float4*)(w2 + (size_t)(kc2*48 + r)*384 + half*192) + c4);
                    }
                    cpa_commit();
                }
                cpa_wait<0>();
                __syncthreads();

                #pragma unroll 4
                for (int kk = 0; kk < 48; kk++){
                    const u64* wrow = (const u64*)(ws + kk*192);
                    u64 wp0 = wrow[lane], wp1 = wrow[lane+32], wp2 = wrow[lane+64];
                    const float* hk = xw + (kc2*48 + kk)*12 + tp*4;
                    #pragma unroll
                    for (int t = 0; t < 4; t++){
                        u64 hv = dup2(hk[t]);
                        fma2(acc2[t][0], hv, wp0);
                        fma2(acc2[t][1], hv, wp1);
                        fma2(acc2[t][2], hv, wp2);
                    }
                }
            }

            // ---- epilogue for this (half, tp): q == half, tokens tp*4.. ----
            if (p0 + tp*4 < HW && !(half == 0 && j == 0)){
                const int dr = half ? srcB : srcA;
                float bias[6];
                #pragma unroll
                for (int p = 0; p < 3; p++){
                    int c = 2*(half*96 + lane + 32*p);
                    bias[2*p] = b2[c]; bias[2*p+1] = b2[c+1];
                }
                float lsum[6] = {0.f,0.f,0.f,0.f,0.f,0.f};
                for (int t = 0; t < 4; t++){
                    int pos = p0 + tp*4 + t;
                    if (pos >= HW) break;
                    unsigned rowoff;
                    if (AXIS == 0) rowoff = (unsigned)((b*HW + dr)*HW + pos)*NC;
                    else           rowoff = (unsigned)((b*HW + pos)*HW + dr)*NC;
                    #pragma unroll
                    for (int p = 0; p < 3; p++){
                        float2 v = unpk(acc2[t][p]);
                        int cc = 2*(lane + 32*p);
                        float2 st;
                        st.x = v.x + bias[2*p];
                        st.y = v.y + bias[2*p+1];
                        *(float2*)(obuf + rowoff + cc) = st;
                        lsum[2*p]   += st.x;
                        lsum[2*p+1] += st.y;
                    }
                }
                #pragma unroll
                for (int i = 0; i < 6; i++){
                    int cc = 2*(lane + 32*(i>>1)) + (i&1);
                    atomicAdd(&g_hwsum[b*NC + cc], lsum[i]);
                }
            }
        }
    }
}

__global__ void gate_kernel(const float* __restrict__ wc,  const float* __restrict__ bc,
                            const float* __restrict__ wa1, const float* __restrict__ ba1,
                            const float* __restrict__ wa2, const float* __restrict__ ba2)
{
    __shared__ float av[NC];
    __shared__ float hid[48];
    const int b = blockIdx.x, t = threadIdx.x;
    const float invN = 1.0f/(float)(HW*HW);
    float s = 0.f;
    for (int k = 0; k < NC; k++) s += g_xsum[b*NC + k]*wc[k*NC + t];
    av[t] = (g_hwsum[b*NC + t] + s)*invN + bc[t];
    __syncthreads();
    if (t < 48){
        float u = ba1[t];
        for (int k = 0; k < NC; k++) u += av[k]*wa1[k*48 + t];
        hid[t] = 0.5f*u*(1.0f + tanhf(0.7978845608028654f*(u + 0.044715f*u*u*u)));
    }
    __syncthreads();
    float v0 = ba2[t*3+0], v1 = ba2[t*3+1], v2 = ba2[t*3+2];
    for (int k = 0; k < 48; k++){
        float hk = hid[k];
        v0 += hk*wa2[k*576 + t*3 + 0];
        v1 += hk*wa2[k*576 + t*3 + 1];
        v2 += hk*wa2[k*576 + t*3 + 2];
    }
    float mx = fmaxf(v0, fmaxf(v1, v2));
    float e0 = expf(v0-mx), e1 = expf(v1-mx), e2 = expf(v2-mx);
    float inv = 1.0f/(e0+e1+e2);
    g_a[b*NC + t]           = e0*inv;
    g_a[NB*NC + b*NC + t]   = e1*inv;
    g_a[2*NB*NC + b*NC + t] = e2*inv;
}

// Final kernel: R9-measured version (16 tokens/block, static smem).
__global__ void __launch_bounds__(192)
final_kernel(const float* __restrict__ x,  const float* __restrict__ wc,
             const float* __restrict__ bc, const float* __restrict__ wo,
             const float* __restrict__ bo, float* __restrict__ out)
{
    __shared__ __align__(16) float xsp[NC*20];
    __shared__ __align__(16) float msp[NC*20];
    const int ch = threadIdx.x;
    const long long tok0 = (long long)blockIdx.x * FT;
    #pragma unroll
    for (int t = 0; t < FT; t++){
        long long tok = tok0 + t; if (tok >= NTOK) tok = NTOK-1;
        xsp[ch*20 + t] = x[tok*NC + ch];
    }
    __syncthreads();
    u64 cacc[8];
    #pragma unroll
    for (int u = 0; u < 8; u++) cacc[u] = 0;
    #pragma unroll 4
    for (int k = 0; k < NC; k++){
        u64 wv = dup2(wc[k*NC + ch]);
        const ulonglong2* xp = (const ulonglong2*)(xsp + k*20);
        ulonglong2 xa = xp[0], xb = xp[1], xc2 = xp[2], xd = xp[3];
        fma2(cacc[0], xa.x, wv); fma2(cacc[1], xa.y, wv);
        fma2(cacc[2], xb.x, wv); fma2(cacc[3], xb.y, wv);
        fma2(cacc[4], xc2.x, wv); fma2(cacc[5], xc2.y, wv);
        fma2(cacc[6], xd.x, wv); fma2(cacc[7], xd.y, wv);
    }
    const float bcv = bc[ch];
    #pragma unroll
    for (int u = 0; u < 8; u++){
        float2 cv = unpk(cacc[u]);
        #pragma unroll
        for (int e = 0; e < 2; e++){
            int t = 2*u + e;
            long long tok = tok0 + t;
            float m = 0.f;
            if (tok < NTOK){
                int bb = (int)(tok / (HW*HW));
                float a0 = g_a[bb*NC + ch];
                float a1 = g_a[NB*NC + bb*NC + ch];
                float a2 = g_a[2*NB*NC + bb*NC + ch];
                float cval = (e ? cv.y : cv.x) + bcv;
                m = g_h[tok*NC + ch]*a0 + g_w[tok*NC + ch]*a1 + cval*a2;
            }
            msp[ch*20 + t] = m;
        }
    }
    __syncthreads();
    u64 oacc[8];
    #pragma unroll
    for (int u = 0; u < 8; u++) oacc[u] = 0;
    #pragma unroll 4
    for (int k = 0; k < NC; k++){
        u64 wv = dup2(wo[k*NC + ch]);
        const ulonglong2* mp = (const ulonglong2*)(msp + k*20);
        ulonglong2 xa = mp[0], xb = mp[1], xc2 = mp[2], xd = mp[3];
        fma2(oacc[0], xa.x, wv); fma2(oacc[1], xa.y, wv);
        fma2(oacc[2], xb.x, wv); fma2(oacc[3], xb.y, wv);
        fma2(oacc[4], xc2.x, wv); fma2(oacc[5], xc2.y, wv);
        fma2(oacc[6], xd.x, wv); fma2(oacc[7], xd.y, wv);
    }
    const float bov = bo[ch];
    #pragma unroll
    for (int u = 0; u < 8; u++){
        float2 ov = unpk(oacc[u]);
        #pragma unroll
        for (int e = 0; e < 2; e++){
            long long tok = tok0 + 2*u + e;
            if (tok < NTOK) out[tok*NC + ch] = (e ? ov.y : ov.x) + bov;
        }
    }
}

extern "C" void kernel_launch(void* const* d_in, const int* in_sizes, int n_in,
                              void* d_out, int out_size)
{
    (void)in_sizes; (void)n_in; (void)out_size;
    const float* x   = (const float*)d_in[0];
    const float* wh1 = (const float*)d_in[1];
    const float* gh  = (const float*)d_in[2];
    const float* bh  = (const float*)d_in[3];
    const float* wh2 = (const float*)d_in[4];
    const float* bh2 = (const float*)d_in[5];
    const float* ww1 = (const float*)d_in[6];
    const float* gw  = (const float*)d_in[7];
    const float* bw  = (const float*)d_in[8];
    const float* ww2 = (const float*)d_in[9];
    const float* bw2 = (const float*)d_in[10];
    const float* wc  = (const float*)d_in[11];
    const float* bc  = (const float*)d_in[12];
    const float* wa1 = (const float*)d_in[13];
    const float* ba1 = (const float*)d_in[14];
    const float* wa2 = (const float*)d_in[15];
    const float* ba2 = (const float*)d_in[16];
    const float* wo  = (const float*)d_in[17];
    const float* bo  = (const float*)d_in[18];
    float* out = (float*)d_out;

    const int shmem_b = (9216 + 8*1152) * 4;   // 73,728 B
    cudaFuncSetAttribute(branch_kernel<0>, cudaFuncAttributeMaxDynamicSharedMemorySize, shmem_b);
    cudaFuncSetAttribute(branch_kernel<1>, cudaFuncAttributeMaxDynamicSharedMemorySize, shmem_b);

    zero_kernel<<<6, 256>>>();
    xsum_kernel<<<dim3(HW, NB), NC>>>(x);
    branch_kernel<0><<<dim3(4, NT, NB), 256, shmem_b>>>(x, wh1, gh, bh, wh2, bh2);
    branch_kernel<1><<<dim3(4, NT, NB), 256, shmem_b>>>(x, ww1, gw, bw, ww2, bw2);
    gate_kernel<<<NB, NC>>>(wc, bc, wa1, ba1, wa2, ba2);
    final_kernel<<<(NTOK + FT - 1)/FT, NC>>>(x, wc, bc, wo, bo, out);
}

// round 16
// speedup vs baseline: 1.2872x; 1.2872x over previous
#include <cuda_runtime.h>
#include <cstdint>
#include <cstddef>

#define DEV __device__ __forceinline__
#define NB   8
#define HW   225
#define NC   192
#define NT   113
#define NTOK (NB*HW*HW)
#define FT   16

__device__ float g_h[NB*HW*HW*NC];
__device__ float g_w[NB*HW*HW*NC];
__device__ float g_xsum[NB*NC];
__device__ float g_hwsum[NB*NC];
__device__ float g_a[3*NB*NC];

typedef unsigned long long u64;

DEV u64 pack2(float a, float b){
    u64 r; asm("mov.b64 %0, {%1, %2};" : "=l"(r)
               : "r"(__float_as_uint(a)), "r"(__float_as_uint(b))); return r;
}
DEV u64 dup2(float a){
    u64 r; asm("mov.b64 %0, {%1, %1};" : "=l"(r) : "r"(__float_as_uint(a))); return r;
}
DEV float2 unpk(u64 v){
    unsigned lo, hi; asm("mov.b64 {%0, %1}, %2;" : "=r"(lo), "=r"(hi) : "l"(v));
    return make_float2(__uint_as_float(lo), __uint_as_float(hi));
}
DEV void fma2(u64 &d, u64 a, u64 b){
    asm("fma.rn.f32x2 %0, %1, %2, %0;" : "+l"(d) : "l"(a), "l"(b));
}

// ---- cp.async helpers ----
DEV void cpa16(void* sdst, const void* gsrc){
    unsigned a = (unsigned)__cvta_generic_to_shared(sdst);
    asm volatile("cp.async.cg.shared.global [%0], [%1], 16;" :: "r"(a), "l"(gsrc));
}
DEV void cpa_commit(){ asm volatile("cp.async.commit_group;"); }
template<int N> DEV void cpa_wait(){ asm volatile("cp.async.wait_group %0;" :: "n"(N)); }

__global__ void zero_kernel(){
    int i = blockIdx.x*blockDim.x + threadIdx.x;
    if (i < NB*NC){ g_xsum[i] = 0.f; g_hwsum[i] = 0.f; }
}

__global__ void xsum_kernel(const float* __restrict__ x){
    int i = blockIdx.x, b = blockIdx.y, ch = threadIdx.x;
    const float* p = x + ((size_t)((b*HW + i)*HW))*NC + ch;
    float s = 0.f;
    for (int w = 0; w < HW; w++) s += p[(size_t)w*NC];
    atomicAdd(&g_xsum[b*NC + ch], s);
}

// Stage weights for stage s (0..7) into buf via cp.async:
//   s in [0,4): w1 rows [s*96, s*96+96)
//   s in [4,8): w2 rows [kc2*48,+48) x cols [half*192,+192), half=(s-4)/2, kc2=(s-4)%2
DEV void stage_w(int s, float* buf, const float* w1, const float* w2, int tid){
    if (s < 4){
        const float4* src = (const float4*)(w1 + s*9216) + tid;
        float4* dst = (float4*)buf + tid;
        #pragma unroll
        for (int i = 0; i < 9; i++) cpa16(dst + 256*i, src + 256*i);
    } else {
        const int half = (s-4) >> 1, kc2 = (s-4) & 1;
        #pragma unroll
        for (int ii = 0; ii < 9; ii++){
            int i = tid + 256*ii;
            int r = i/48, c4 = i%48;
            cpa16((float4*)buf + i,
                  (const float4*)(w2 + (size_t)(kc2*48 + r)*384 + half*192) + c4);
        }
    }
}

// Cooperative branch kernel (R11-measured config): cp.async double-buffered
// weight staging, 8 warps/block, each warp = 8 tokens of tile j.
template<int AXIS>
__global__ void __launch_bounds__(256, 2)
branch_kernel(const float* __restrict__ x,  const float* __restrict__ w1,
              const float* __restrict__ gln, const float* __restrict__ bln,
              const float* __restrict__ w2,  const float* __restrict__ b2)
{
    extern __shared__ __align__(16) float smem[];
    float* wsb[2] = { smem, smem + 9216 };            // 2 x 36.8 KB ping-pong
    float* xw = smem + 18432 + (threadIdx.x >> 5) * 1152;  // per-warp 96*12

    const int tid  = threadIdx.x;
    const int lane = tid & 31;
    const int b = blockIdx.z, j = blockIdx.y;
    const int p0 = blockIdx.x*64 + (tid >> 5)*8;
    float* obuf = (AXIS == 0) ? g_h : g_w;
    const int srcA = (j + HW - 2) % HW;
    const int srcB = (j + NT - 2) % HW;

    stage_w(0, wsb[0], w1, w2, tid); cpa_commit();

    // ================= GEMM1: 384 -> 96, 4 chunks of 96 k =================
    u64 acc1[4][3];
    #pragma unroll
    for (int u = 0; u < 4; u++){ acc1[u][0]=0; acc1[u][1]=0; acc1[u][2]=0; }

    #pragma unroll
    for (int kc = 0; kc < 4; kc++){
        {   // stage x chunk kc (per-warp LDG->STS)
            const int src = (kc < 2) ? srcA : srcB;
            const int choff = (kc & 1) * 96;
            #pragma unroll
            for (int t = 0; t < 8; t++){
                int pos = p0 + t; if (pos > HW-1) pos = HW-1;
                size_t base;
                if (AXIS == 0) base = ((size_t)((b*HW + src)*HW + pos))*NC + choff;
                else           base = ((size_t)((b*HW + pos)*HW + src))*NC + choff;
                #pragma unroll
                for (int i = 0; i < 3; i++){
                    int cl = lane + 32*i;
                    xw[cl*12 + t] = x[base + cl];
                }
            }
        }
        stage_w(kc+1, wsb[(kc+1)&1], w1, w2, tid); cpa_commit();
        cpa_wait<1>();
        __syncthreads();

        const float* ws = wsb[kc&1];
        #pragma unroll 4
        for (int kk = 0; kk < 96; kk++){
            const float* wr = ws + kk*96;
            u64 wd0 = dup2(wr[lane]);
            u64 wd1 = dup2(wr[lane+32]);
            u64 wd2 = dup2(wr[lane+64]);
            const ulonglong2* xp = (const ulonglong2*)(xw + kk*12);
            ulonglong2 xa = xp[0], xb = xp[1];
            fma2(acc1[0][0], xa.x, wd0); fma2(acc1[0][1], xa.x, wd1); fma2(acc1[0][2], xa.x, wd2);
            fma2(acc1[1][0], xa.y, wd0); fma2(acc1[1][1], xa.y, wd1); fma2(acc1[1][2], xa.y, wd2);
            fma2(acc1[2][0], xb.x, wd0); fma2(acc1[2][1], xb.x, wd1); fma2(acc1[2][2], xb.x, wd2);
            fma2(acc1[3][0], xb.y, wd0); fma2(acc1[3][1], xb.y, wd1); fma2(acc1[3][2], xb.y, wd2);
        }
        __syncthreads();   // buf[kc&1] free for restage at kc+2
    }

    // ---- LayerNorm(96) + relu -> hs (overlays xw) ----
    {
        float gv0 = gln[lane], gv1 = gln[lane+32], gv2 = gln[lane+64];
        float bv0 = bln[lane], bv1 = bln[lane+32], bv2 = bln[lane+64];
        u64* hp = (u64*)xw;
        #pragma unroll
        for (int u = 0; u < 4; u++){
            float2 v0 = unpk(acc1[u][0]), v1 = unpk(acc1[u][1]), v2 = unpk(acc1[u][2]);
            float sx = v0.x+v1.x+v2.x, sy = v0.y+v1.y+v2.y;
            float qx = v0.x*v0.x+v1.x*v1.x+v2.x*v2.x;
            float qy = v0.y*v0.y+v1.y*v1.y+v2.y*v2.y;
            #pragma unroll
            for (int o = 16; o > 0; o >>= 1){
                sx += __shfl_xor_sync(0xffffffffu, sx, o);
                sy += __shfl_xor_sync(0xffffffffu, sy, o);
                qx += __shfl_xor_sync(0xffffffffu, qx, o);
                qy += __shfl_xor_sync(0xffffffffu, qy, o);
            }
            const float inv = 1.0f/96.0f;
            float mx = sx*inv, my = sy*inv;
            float rx = rsqrtf(fmaxf(qx*inv - mx*mx, 0.f) + 1e-6f);
            float ry = rsqrtf(fmaxf(qy*inv - my*my, 0.f) + 1e-6f);
            float hx, hy;
            hx = fmaxf((v0.x-mx)*rx*gv0+bv0, 0.f); hy = fmaxf((v0.y-my)*ry*gv0+bv0, 0.f);
            hp[lane*6 + u] = pack2(hx, hy);
            hx = fmaxf((v1.x-mx)*rx*gv1+bv1, 0.f); hy = fmaxf((v1.y-my)*ry*gv1+bv1, 0.f);
            hp[(lane+32)*6 + u] = pack2(hx, hy);
            hx = fmaxf((v2.x-mx)*rx*gv2+bv2, 0.f); hy = fmaxf((v2.y-my)*ry*gv2+bv2, 0.f);
            hp[(lane+64)*6 + u] = pack2(hx, hy);
        }
    }
    __syncwarp();

    // ====== GEMM2: 96 -> 384, two output halves, stages 4..7 ====
    #pragma unroll
    for (int half = 0; half < 2; half++){
        u64 acc2[8][3];
        #pragma unroll
        for (int t = 0; t < 8; t++){ acc2[t][0]=0; acc2[t][1]=0; acc2[t][2]=0; }

        #pragma unroll
        for (int kc2 = 0; kc2 < 2; kc2++){
            const int s = 4 + half*2 + kc2;
            if (s < 7){ stage_w(s+1, wsb[(s+1)&1], w1, w2, tid); cpa_commit(); cpa_wait<1>(); }
            else      { cpa_wait<0>(); }
            __syncthreads();

            const float* ws = wsb[s&1];
            #pragma unroll 2
            for (int kk = 0; kk < 48; kk++){
                const u64* wrow = (const u64*)(ws + kk*192);
                u64 wp0 = wrow[lane], wp1 = wrow[lane+32], wp2 = wrow[lane+64];
                const float* hk = xw + (kc2*48 + kk)*12;
                #pragma unroll
                for (int t = 0; t < 8; t++){
                    u64 hv = dup2(hk[t]);
                    fma2(acc2[t][0], hv, wp0);
                    fma2(acc2[t][1], hv, wp1);
                    fma2(acc2[t][2], hv, wp2);
                }
            }
            __syncthreads();
        }

        if (p0 < HW && !(half == 0 && j == 0)){
            const int dr = half ? srcB : srcA;
            float bias[6];
            #pragma unroll
            for (int p = 0; p < 3; p++){
                int c = 2*(half*96 + lane + 32*p);
                bias[2*p] = b2[c]; bias[2*p+1] = b2[c+1];
            }
            float lsum[6] = {0.f,0.f,0.f,0.f,0.f,0.f};
            for (int t = 0; t < 8; t++){
                int pos = p0 + t;
                if (pos >= HW) break;
                size_t rowoff;
                if (AXIS == 0) rowoff = ((size_t)((b*HW + dr)*HW + pos))*NC;
                else           rowoff = ((size_t)((b*HW + pos)*HW + dr))*NC;
                #pragma unroll
                for (int p = 0; p < 3; p++){
                    float2 v = unpk(acc2[t][p]);
                    int cc = 2*(lane + 32*p);
                    float2 st;
                    st.x = v.x + bias[2*p];
                    st.y = v.y + bias[2*p+1];
                    *(float2*)(obuf + rowoff + cc) = st;
                    lsum[2*p]   += st.x;
                    lsum[2*p+1] += st.y;
                }
            }
            #pragma unroll
            for (int i = 0; i < 6; i++){
                int cc = 2*(lane + 32*(i>>1)) + (i&1);
                atomicAdd(&g_hwsum[b*NC + cc], lsum[i]);
            }
        }
    }
}

__global__ void gate_kernel(const float* __restrict__ wc,  const float* __restrict__ bc,
                            const float* __restrict__ wa1, const float* __restrict__ ba1,
                            const float* __restrict__ wa2, const float* __restrict__ ba2)
{
    __shared__ float av[NC];
    __shared__ float hid[48];
    const int b = blockIdx.x, t = threadIdx.x;
    const float invN = 1.0f/(float)(HW*HW);
    float s = 0.f;
    for (int k = 0; k < NC; k++) s += g_xsum[b*NC + k]*wc[k*NC + t];
    av[t] = (g_hwsum[b*NC + t] + s)*invN + bc[t];
    __syncthreads();
    if (t < 48){
        float u = ba1[t];
        for (int k = 0; k < NC; k++) u += av[k]*wa1[k*48 + t];
        hid[t] = 0.5f*u*(1.0f + tanhf(0.7978845608028654f*(u + 0.044715f*u*u*u)));
    }
    __syncthreads();
    float v0 = ba2[t*3+0], v1 = ba2[t*3+1], v2 = ba2[t*3+2];
    for (int k = 0; k < 48; k++){
        float hk = hid[k];
        v0 += hk*wa2[k*576 + t*3 + 0];
        v1 += hk*wa2[k*576 + t*3 + 1];
        v2 += hk*wa2[k*576 + t*3 + 2];
    }
    float mx = fmaxf(v0, fmaxf(v1, v2));
    float e0 = expf(v0-mx), e1 = expf(v1-mx), e2 = expf(v2-mx);
    float inv = 1.0f/(e0+e1+e2);
    g_a[b*NC + t]           = e0*inv;
    g_a[NB*NC + b*NC + t]   = e1*inv;
    g_a[2*NB*NC + b*NC + t] = e2*inv;
}

// Final kernel: R9 structure + register double-buffered weight prefetch.
// k-loop in groups of 8; next group's weights LDG'd at group start so the
// ~240cyc L2 hit overlaps ~176cyc of FFMA2 work.
__global__ void __launch_bounds__(192)
final_kernel(const float* __restrict__ x,  const float* __restrict__ wc,
             const float* __restrict__ bc, const float* __restrict__ wo,
             const float* __restrict__ bo, float* __restrict__ out)
{
    __shared__ __align__(16) float xsp[NC*20];
    __shared__ __align__(16) float msp[NC*20];
    const int ch = threadIdx.x;
    const long long tok0 = (long long)blockIdx.x * FT;
    #pragma unroll
    for (int t = 0; t < FT; t++){
        long long tok = tok0 + t; if (tok >= NTOK) tok = NTOK-1;
        xsp[ch*20 + t] = x[tok*NC + ch];
    }
    __syncthreads();

    // ---- GEMM1: c = x @ wc ----
    u64 cacc[8];
    #pragma unroll
    for (int u = 0; u < 8; u++) cacc[u] = 0;
    {
        float wreg[8], wnxt[8];
        #pragma unroll
        for (int i = 0; i < 8; i++) wreg[i] = wc[i*NC + ch];
        for (int kg = 0; kg < 24; kg++){
            const int kb = (kg < 23) ? (kg+1)*8 : 184;
            #pragma unroll
            for (int i = 0; i < 8; i++) wnxt[i] = wc[(kb+i)*NC + ch];
            #pragma unroll
            for (int i = 0; i < 8; i++){
                const int k = kg*8 + i;
                u64 wv = dup2(wreg[i]);
                const ulonglong2* xp = (const ulonglong2*)(xsp + k*20);
                ulonglong2 xa = xp[0], xb = xp[1], xc2 = xp[2], xd = xp[3];
                fma2(cacc[0], xa.x, wv); fma2(cacc[1], xa.y, wv);
                fma2(cacc[2], xb.x, wv); fma2(cacc[3], xb.y, wv);
                fma2(cacc[4], xc2.x, wv); fma2(cacc[5], xc2.y, wv);
                fma2(cacc[6], xd.x, wv); fma2(cacc[7], xd.y, wv);
            }
            #pragma unroll
            for (int i = 0; i < 8; i++) wreg[i] = wnxt[i];
        }
    }

    const float bcv = bc[ch];
    #pragma unroll
    for (int u = 0; u < 8; u++){
        float2 cv = unpk(cacc[u]);
        #pragma unroll
        for (int e = 0; e < 2; e++){
            int t = 2*u + e;
            long long tok = tok0 + t;
            float m = 0.f;
            if (tok < NTOK){
                int bb = (int)(tok / (HW*HW));
                float a0 = g_a[bb*NC + ch];
                float a1 = g_a[NB*NC + bb*NC + ch];
                float a2 = g_a[2*NB*NC + bb*NC + ch];
                float cval = (e ? cv.y : cv.x) + bcv;
                m = g_h[tok*NC + ch]*a0 + g_w[tok*NC + ch]*a1 + cval*a2;
            }
            msp[ch*20 + t] = m;
        }
    }
    __syncthreads();

    // ---- GEMM2: out = m @ wo ----
    u64 oacc[8];
    #pragma unroll
    for (int u = 0; u < 8; u++) oacc[u] = 0;
    {
        float wreg[8], wnxt[8];
        #pragma unroll
        for (int i = 0; i < 8; i++) wreg[i] = wo[i*NC + ch];
        for (int kg = 0; kg < 24; kg++){
            const int kb = (kg < 23) ? (kg+1)*8 : 184;
            #pragma unroll
            for (int i = 0; i < 8; i++) wnxt[i] = wo[(kb+i)*NC + ch];
            #pragma unroll
            for (int i = 0; i < 8; i++){
                const int k = kg*8 + i;
                u64 wv = dup2(wreg[i]);
                const ulonglong2* mp = (const ulonglong2*)(msp + k*20);
                ulonglong2 xa = mp[0], xb = mp[1], xc2 = mp[2], xd = mp[3];
                fma2(oacc[0], xa.x, wv); fma2(oacc[1], xa.y, wv);
                fma2(oacc[2], xb.x, wv); fma2(oacc[3], xb.y, wv);
                fma2(oacc[4], xc2.x, wv); fma2(oacc[5], xc2.y, wv);
                fma2(oacc[6], xd.x, wv); fma2(oacc[7], xd.y, wv);
            }
            #pragma unroll
            for (int i = 0; i < 8; i++) wreg[i] = wnxt[i];
        }
    }

    const float bov = bo[ch];
    #pragma unroll
    for (int u = 0; u < 8; u++){
        float2 ov = unpk(oacc[u]);
        #pragma unroll
        for (int e = 0; e < 2; e++){
            long long tok = tok0 + 2*u + e;
            if (tok < NTOK) out[tok*NC + ch] = (e ? ov.y : ov.x) + bov;
        }
    }
}

extern "C" void kernel_launch(void* const* d_in, const int* in_sizes, int n_in,
                              void* d_out, int out_size)
{
    (void)in_sizes; (void)n_in; (void)out_size;
    const float* x   = (const float*)d_in[0];
    const float* wh1 = (const float*)d_in[1];
    const float* gh  = (const float*)d_in[2];
    const float* bh  = (const float*)d_in[3];
    const float* wh2 = (const float*)d_in[4];
    const float* bh2 = (const float*)d_in[5];
    const float* ww1 = (const float*)d_in[6];
    const float* gw  = (const float*)d_in[7];
    const float* bw  = (const float*)d_in[8];
    const float* ww2 = (const float*)d_in[9];
    const float* bw2 = (const float*)d_in[10];
    const float* wc  = (const float*)d_in[11];
    const float* bc  = (const float*)d_in[12];
    const float* wa1 = (const float*)d_in[13];
    const float* ba1 = (const float*)d_in[14];
    const float* wa2 = (const float*)d_in[15];
    const float* ba2 = (const float*)d_in[16];
    const float* wo  = (const float*)d_in[17];
    const float* bo  = (const float*)d_in[18];
    float* out = (float*)d_out;

    const int shmem_b = (2*9216 + 8*1152) * 4;   // 110,592 B
    cudaFuncSetAttribute(branch_kernel<0>, cudaFuncAttributeMaxDynamicSharedMemorySize, shmem_b);
    cudaFuncSetAttribute(branch_kernel<1>, cudaFuncAttributeMaxDynamicSharedMemorySize, shmem_b);

    zero_kernel<<<6, 256>>>();
    xsum_kernel<<<dim3(HW, NB), NC>>>(x);
    branch_kernel<0><<<dim3(4, NT, NB), 256, shmem_b>>>(x, wh1, gh, bh, wh2, bh2);
    branch_kernel<1><<<dim3(4, NT, NB), 256, shmem_b>>>(x, ww1, gw, bw, ww2, bw2);
    gate_kernel<<<NB, NC>>>(wc, bc, wa1, ba1, wa2, ba2);
    final_kernel<<<(NTOK + FT - 1)/FT, NC>>>(x, wc, bc, wo, bo, out);
}